// round 1
// baseline (speedup 1.0000x reference)
#include <cuda_runtime.h>
#include <cstdint>

#define HH 64
#define TT 9
#define NMAX 50048
#define NEMAX 250016

// ---------------- scratch (device globals; no runtime allocation) ----------------
__device__ __align__(256) float g_Q[NMAX * HH];
__device__ __align__(256) float g_K[NMAX * HH];
__device__ __align__(256) float g_V[NMAX * HH];
__device__ __align__(256) float g_out1[NMAX * HH];
__device__ __align__(256) float g_out2[NMAX * HH];
__device__ __align__(256) float g_out3[NMAX * HH];
__device__ __align__(256) float g_x1[NMAX * HH];
__device__ __align__(256) float g_x2[NMAX * HH];
__device__ __align__(256) float g_x3[NMAX * HH];
__device__ __align__(256) float g_alpha[NEMAX];
__device__ __align__(256) float g_wbuf[NEMAX];
__device__ __align__(256) unsigned g_mx[NMAX];
__device__ __align__(256) float g_den[NMAX];
__device__ __align__(256) float g_Wsum[HH * HH];
__device__ __align__(256) float g_bsum[HH];

// ---------------- helpers ----------------
__device__ __forceinline__ unsigned fenc(float f) {
    unsigned u = __float_as_uint(f);
    return (u & 0x80000000u) ? ~u : (u | 0x80000000u);
}
__device__ __forceinline__ float fdec(unsigned u) {
    return (u & 0x80000000u) ? __uint_as_float(u ^ 0x80000000u) : __uint_as_float(~u);
}

// ---------------- GEMM: Out[N,64] = X[N,64] @ W[64,64] + B[64] ----------------
// Block 128 threads, tile 128 rows x 64 cols, 8x8 register blocking.
#define GEMM_SMEM ((128 * 65 + 64 * 64) * 4)

__global__ void __launch_bounds__(128, 4) gemm64(
    const float* __restrict__ X, const float* __restrict__ W,
    const float* __restrict__ B, float* __restrict__ Out, int N)
{
    extern __shared__ float sm[];
    float* Xs = sm;               // [128][65] padded
    float* Ws = sm + 128 * 65;    // [64][64]
    const int tid = threadIdx.x;
    const int row0 = blockIdx.x * 128;

    // load W (4096 floats)
    {
        const float4* W4 = (const float4*)W;
        float4* Ws4 = (float4*)Ws;
#pragma unroll
        for (int i = 0; i < 8; ++i) Ws4[i * 128 + tid] = W4[i * 128 + tid];
    }
    // load X tile (rows row0..row0+127), zero-pad out-of-range rows
    {
        const float4* X4 = (const float4*)X;
#pragma unroll
        for (int i = 0; i < 16; ++i) {
            int id = i * 128 + tid;   // 0..2047 float4s
            int r = id >> 4;
            int k4 = id & 15;
            float4 v = make_float4(0.f, 0.f, 0.f, 0.f);
            if (row0 + r < N) v = X4[(size_t)(row0 + r) * 16 + k4];
            float* dst = Xs + r * 65 + k4 * 4;
            dst[0] = v.x; dst[1] = v.y; dst[2] = v.z; dst[3] = v.w;
        }
    }
    __syncthreads();

    const int tx = tid & 7;   // 8 col-groups of 8
    const int ty = tid >> 3;  // 16 row-groups of 8
    float acc[8][8];
#pragma unroll
    for (int i = 0; i < 8; ++i)
#pragma unroll
        for (int j = 0; j < 8; ++j) acc[i][j] = 0.f;

#pragma unroll 8
    for (int k = 0; k < 64; ++k) {
        float xf[8];
#pragma unroll
        for (int i = 0; i < 8; ++i) xf[i] = Xs[(ty * 8 + i) * 65 + k];
        float4 wa = *(const float4*)(Ws + k * 64 + tx * 8);
        float4 wb = *(const float4*)(Ws + k * 64 + tx * 8 + 4);
        float wf[8] = {wa.x, wa.y, wa.z, wa.w, wb.x, wb.y, wb.z, wb.w};
#pragma unroll
        for (int i = 0; i < 8; ++i)
#pragma unroll
            for (int j = 0; j < 8; ++j) acc[i][j] += xf[i] * wf[j];
    }

    float4 ba = *(const float4*)(B + tx * 8);
    float4 bb = *(const float4*)(B + tx * 8 + 4);
    float bf[8] = {ba.x, ba.y, ba.z, ba.w, bb.x, bb.y, bb.z, bb.w};
#pragma unroll
    for (int i = 0; i < 8; ++i) {
        int r = row0 + ty * 8 + i;
        if (r < N) {
            float4 o0 = make_float4(acc[i][0] + bf[0], acc[i][1] + bf[1],
                                    acc[i][2] + bf[2], acc[i][3] + bf[3]);
            float4 o1 = make_float4(acc[i][4] + bf[4], acc[i][5] + bf[5],
                                    acc[i][6] + bf[6], acc[i][7] + bf[7]);
            float4* O4 = (float4*)(Out + (size_t)r * 64 + tx * 8);
            O4[0] = o0; O4[1] = o1;
        }
    }
}

// ---------------- sum skip weights over edge types with same dest ----------------
__global__ void sumskip(const float* __restrict__ Wl, const float* __restrict__ bl,
                        int t0, int t1, int t2, int t3, int cnt,
                        float* __restrict__ Wsum, float* __restrict__ bsum)
{
    int i = blockIdx.x * blockDim.x + threadIdx.x;
    int ts[4] = {t0, t1, t2, t3};
    if (i < 4096) {
        float s = 0.f;
        for (int j = 0; j < cnt; ++j) s += Wl[ts[j] * 4096 + i];
        Wsum[i] = s;
        if (i < 64) {
            float sb = 0.f;
            for (int j = 0; j < cnt; ++j) sb += bl[ts[j] * 64 + i];
            bsum[i] = sb;
        }
    }
}

// ---------------- per-edge-type softmax state init ----------------
__global__ void init_md(unsigned* __restrict__ mx, float* __restrict__ den, int N)
{
    int i = blockIdx.x * blockDim.x + threadIdx.x;
    if (i < N) { mx[i] = 0x007FFFFFu; /* enc(-inf) */ den[i] = 0.f; }
}

// ---------------- pass A: alpha + atomic segment max. 2 edges / warp ----------------
__global__ void pass_a(const float* __restrict__ Q, const float* __restrict__ K,
                       const int* __restrict__ src, const int* __restrict__ dst,
                       const float* __restrict__ eattr, const float* __restrict__ We,
                       float* __restrict__ alpha, unsigned* __restrict__ gmax, int NE)
{
    __shared__ __align__(16) float sWe[128];
    int tid = threadIdx.x;
    if (tid < 128) sWe[tid] = We[tid];
    __syncthreads();

    int l16 = tid & 15;
    int e = blockIdx.x * (blockDim.x >> 4) + (tid >> 4);
    if (e >= NE) return;
    int s = src[e], d = dst[e];
    float2 ea = ((const float2*)eattr)[e];
    float4 q = ((const float4*)Q)[d * 16 + l16];
    float4 k = ((const float4*)K)[s * 16 + l16];
    float4 w0 = ((const float4*)sWe)[l16];
    float4 w1 = ((const float4*)sWe)[16 + l16];
    float dotv = q.x * (k.x + ea.x * w0.x + ea.y * w1.x)
               + q.y * (k.y + ea.x * w0.y + ea.y * w1.y)
               + q.z * (k.z + ea.x * w0.z + ea.y * w1.z)
               + q.w * (k.w + ea.x * w0.w + ea.y * w1.w);
    unsigned hm = (tid & 16) ? 0xFFFF0000u : 0x0000FFFFu;
#pragma unroll
    for (int off = 8; off >= 1; off >>= 1)
        dotv += __shfl_down_sync(hm, dotv, off, 16);
    if (l16 == 0) {
        float a = dotv * 0.125f;  // 1/sqrt(64)
        alpha[e] = a;
        atomicMax(gmax + d, fenc(a));
    }
}

// ---------------- pass B: exp + atomic denom ----------------
__global__ void pass_b(const float* __restrict__ alpha, const int* __restrict__ dst,
                       const unsigned* __restrict__ gmax, float* __restrict__ wbuf,
                       float* __restrict__ den, int NE)
{
    int e = blockIdx.x * blockDim.x + threadIdx.x;
    if (e >= NE) return;
    int d = dst[e];
    float m = fdec(gmax[d]);
    float w = __expf(alpha[e] - m);
    wbuf[e] = w;
    atomicAdd(den + d, w);
}

// ---------------- pass C: weighted scatter of V+e. 2 edges / warp, float4 red ----------------
__global__ void pass_c(const float* __restrict__ V,
                       const int* __restrict__ src, const int* __restrict__ dst,
                       const float* __restrict__ eattr, const float* __restrict__ We,
                       const float* __restrict__ wbuf, const float* __restrict__ den,
                       float* __restrict__ Out, int NE)
{
    __shared__ __align__(16) float sWe[128];
    int tid = threadIdx.x;
    if (tid < 128) sWe[tid] = We[tid];
    __syncthreads();

    int l16 = tid & 15;
    int e = blockIdx.x * (blockDim.x >> 4) + (tid >> 4);
    if (e >= NE) return;
    int s = src[e], d = dst[e];
    float coef = wbuf[e] / (den[d] + 1e-16f);
    float2 ea = ((const float2*)eattr)[e];
    float4 v = ((const float4*)V)[s * 16 + l16];
    float4 w0 = ((const float4*)sWe)[l16];
    float4 w1 = ((const float4*)sWe)[16 + l16];
    float rx = coef * (v.x + ea.x * w0.x + ea.y * w1.x);
    float ry = coef * (v.y + ea.x * w0.y + ea.y * w1.y);
    float rz = coef * (v.z + ea.x * w0.z + ea.y * w1.z);
    float rw = coef * (v.w + ea.x * w0.w + ea.y * w1.w);
    float* p = Out + (size_t)d * 64 + l16 * 4;
    asm volatile("red.global.add.v4.f32 [%0], {%1,%2,%3,%4};"
                 :: "l"(p), "f"(rx), "f"(ry), "f"(rz), "f"(rw) : "memory");
}

// ---------------- relu copy ----------------
__global__ void relu_copy(const float* __restrict__ in, float* __restrict__ out, int n4)
{
    int i = blockIdx.x * blockDim.x + threadIdx.x;
    if (i >= n4) return;
    float4 v = ((const float4*)in)[i];
    v.x = fmaxf(v.x, 0.f); v.y = fmaxf(v.y, 0.f);
    v.z = fmaxf(v.z, 0.f); v.w = fmaxf(v.w, 0.f);
    ((float4*)out)[i] = v;
}

// ---------------- final linear: out[N,4] = X[N,64] @ W[64,4] + b[4] ----------------
__global__ void final_lin(const float* __restrict__ X, const float* __restrict__ W,
                          const float* __restrict__ b, float* __restrict__ out, int N)
{
    __shared__ float sW[256];
    int tid = threadIdx.x;
    if (tid < 256) sW[tid] = W[tid];
    __syncthreads();
    int warp = tid >> 5, lane = tid & 31;
    int row = blockIdx.x * 8 + warp;
    if (row >= N) return;
    float2 x2 = ((const float2*)(X + (size_t)row * 64))[lane];
    float a0 = x2.x * sW[(2 * lane) * 4 + 0] + x2.y * sW[(2 * lane + 1) * 4 + 0];
    float a1 = x2.x * sW[(2 * lane) * 4 + 1] + x2.y * sW[(2 * lane + 1) * 4 + 1];
    float a2 = x2.x * sW[(2 * lane) * 4 + 2] + x2.y * sW[(2 * lane + 1) * 4 + 2];
    float a3 = x2.x * sW[(2 * lane) * 4 + 3] + x2.y * sW[(2 * lane + 1) * 4 + 3];
#pragma unroll
    for (int off = 16; off >= 1; off >>= 1) {
        a0 += __shfl_down_sync(0xffffffffu, a0, off);
        a1 += __shfl_down_sync(0xffffffffu, a1, off);
        a2 += __shfl_down_sync(0xffffffffu, a2, off);
        a3 += __shfl_down_sync(0xffffffffu, a3, off);
    }
    if (lane == 0) {
        float4 o = make_float4(a0 + b[0], a1 + b[1], a2 + b[2], a3 + b[3]);
        ((float4*)out)[row] = o;
    }
}

// ---------------- host driver ----------------
extern "C" void kernel_launch(void* const* d_in, const int* in_sizes, int n_in,
                              void* d_out, int out_size)
{
    const float* xin[4] = {(const float*)d_in[0], (const float*)d_in[1],
                           (const float*)d_in[2], (const float*)d_in[3]};
    const int*   eidx  = (const int*)d_in[4];
    const float* eattr = (const float*)d_in[5];
    const float* Wq = (const float*)d_in[6];  const float* bq = (const float*)d_in[7];
    const float* Wk = (const float*)d_in[8];  const float* bk = (const float*)d_in[9];
    const float* Wv = (const float*)d_in[10]; const float* bv = (const float*)d_in[11];
    const float* We = (const float*)d_in[12];
    const float* Wsk = (const float*)d_in[13]; const float* bsk = (const float*)d_in[14];
    const float* linW = (const float*)d_in[15]; const float* linb = (const float*)d_in[16];

    const int N  = in_sizes[0] / HH;
    const int NE = in_sizes[5] / (TT * 2);

    float *pQ, *pK, *pV, *pA, *pWb, *pD, *pWs, *pBs;
    float *pO[3], *pX[3];
    unsigned* pM;
    cudaGetSymbolAddress((void**)&pQ, g_Q);
    cudaGetSymbolAddress((void**)&pK, g_K);
    cudaGetSymbolAddress((void**)&pV, g_V);
    cudaGetSymbolAddress((void**)&pO[0], g_out1);
    cudaGetSymbolAddress((void**)&pO[1], g_out2);
    cudaGetSymbolAddress((void**)&pO[2], g_out3);
    cudaGetSymbolAddress((void**)&pX[0], g_x1);
    cudaGetSymbolAddress((void**)&pX[1], g_x2);
    cudaGetSymbolAddress((void**)&pX[2], g_x3);
    cudaGetSymbolAddress((void**)&pA, g_alpha);
    cudaGetSymbolAddress((void**)&pWb, g_wbuf);
    cudaGetSymbolAddress((void**)&pM, g_mx);
    cudaGetSymbolAddress((void**)&pD, g_den);
    cudaGetSymbolAddress((void**)&pWs, g_Wsum);
    cudaGetSymbolAddress((void**)&pBs, g_bsum);

    cudaFuncSetAttribute(gemm64, cudaFuncAttributeMaxDynamicSharedMemorySize, GEMM_SMEM);

    const int gemmGrid = (N + 127) / 128;
    static const int sT[9] = {0, 0, 0, 1, 1, 1, 2, 2, 3};
    static const int dT[9] = {1, 2, 3, 2, 3, 1, 3, 2, 3};

    const float* xcur[4];
    for (int l = 0; l < 2; ++l) {
        xcur[0] = xin[0];
        if (l == 0) { xcur[1] = xin[1]; xcur[2] = xin[2]; xcur[3] = xin[3]; }
        else        { xcur[1] = pX[0];  xcur[2] = pX[1];  xcur[3] = pX[2]; }

        const float* Wsl = Wsk + (size_t)l * TT * 4096;
        const float* bsl = bsk + (size_t)l * TT * 64;

        // skip init: out[d] = x_d @ (sum_t Wskip) + sum_t bskip
        sumskip<<<16, 256>>>(Wsl, bsl, 0, 5, 0, 0, 2, pWs, pBs);
        gemm64<<<gemmGrid, 128, GEMM_SMEM>>>(xcur[1], pWs, pBs, pO[0], N);
        sumskip<<<16, 256>>>(Wsl, bsl, 1, 3, 7, 0, 3, pWs, pBs);
        gemm64<<<gemmGrid, 128, GEMM_SMEM>>>(xcur[2], pWs, pBs, pO[1], N);
        sumskip<<<16, 256>>>(Wsl, bsl, 2, 4, 6, 8, 4, pWs, pBs);
        gemm64<<<gemmGrid, 128, GEMM_SMEM>>>(xcur[3], pWs, pBs, pO[2], N);

        for (int t = 0; t < TT; ++t) {
            int s = sT[t], d = dT[t];
            size_t wo = (size_t)(l * TT + t) * 4096;
            size_t bo = (size_t)(l * TT + t) * 64;
            gemm64<<<gemmGrid, 128, GEMM_SMEM>>>(xcur[d], Wq + wo, bq + bo, pQ, N);
            gemm64<<<gemmGrid, 128, GEMM_SMEM>>>(xcur[s], Wk + wo, bk + bo, pK, N);
            gemm64<<<gemmGrid, 128, GEMM_SMEM>>>(xcur[s], Wv + wo, bv + bo, pV, N);
            init_md<<<(N + 255) / 256, 256>>>(pM, pD, N);

            const int* srcp = eidx + (size_t)t * 2 * NE;
            const int* dstp = srcp + NE;
            const float* eat = eattr + (size_t)t * NE * 2;
            const float* Wet = We + (size_t)(l * TT + t) * 128;

            pass_a<<<(NE + 15) / 16, 256>>>(pQ, pK, srcp, dstp, eat, Wet, pA, pM, NE);
            pass_b<<<(NE + 255) / 256, 256>>>(pA, dstp, pM, pWb, pD, NE);
            pass_c<<<(NE + 15) / 16, 256>>>(pV, srcp, dstp, eat, Wet, pWb, pD, pO[d - 1], NE);
        }

        int n4 = N * 16;
        for (int dd = 0; dd < 3; ++dd)
            relu_copy<<<(n4 + 255) / 256, 256>>>(pO[dd], pX[dd], n4);
    }

    // final linear on PQ (type index 2 -> pX[1])
    final_lin<<<(N + 7) / 8, 256>>>(pX[1], linW, linb, (float*)d_out, N);
}

// round 2
// speedup vs baseline: 1.1087x; 1.1087x over previous
#include <cuda_runtime.h>
#include <cstdint>

#define HH 64
#define TT 9
#define NMAX 50048
#define NEMAX 250016
#define PSTRIDE ((size_t)NMAX * HH)

// ---------------- scratch (device globals; bss, no runtime allocation) ----------------
__device__ __align__(256) float g_P[27 * PSTRIDE];       // per (type,role) projections: idx = t*3+role (0=Q,1=K,2=V)
__device__ __align__(256) float g_outA[3][NMAX * HH];    // layer-1 node outputs (pre-relu)
__device__ __align__(256) float g_outB[3][NMAX * HH];    // layer-2 node outputs (pre-relu)
__device__ __align__(256) float g_alpha[9 * (size_t)NEMAX];
__device__ __align__(256) float g_wbuf[9 * (size_t)NEMAX];
__device__ __align__(256) unsigned g_mx[9 * NMAX];
__device__ __align__(256) float g_den[9 * NMAX];
__device__ __align__(256) float g_Wsum[3 * 4096];
__device__ __align__(256) float g_bsum[3 * 64];

__constant__ int c_dT[9] = {1, 2, 3, 2, 3, 1, 3, 2, 3};

// ---------------- helpers ----------------
__device__ __forceinline__ unsigned fenc(float f) {
    unsigned u = __float_as_uint(f);
    return (u & 0x80000000u) ? ~u : (u | 0x80000000u);
}
__device__ __forceinline__ float fdec(unsigned u) {
    return (u & 0x80000000u) ? __uint_as_float(u ^ 0x80000000u) : __uint_as_float(~u);
}

// ---------------- multi-weight GEMM ----------------
// Out_j[N,64] = X[N,64] @ W_j[64,64] + B_j  for up to 10 weight matrices.
// Block: 256 threads, 128 rows x 128 cols (2 weight mats), 8x8 per thread.
// grid.x = row tiles, grid.y = weight pairs.
struct Job { const float* W; const float* B; float* O; };
struct Jobs { Job j[10]; };

#define GM_SMEM ((128 * 65 + 2 * 64 * 64) * 4)

__global__ void __launch_bounds__(256, 2) gemm_multi(
    const float* __restrict__ X, Jobs jobs, int nmat, int N, int dorelu)
{
    extern __shared__ float sm[];
    float* Xs = sm;                 // [128][65] padded
    float* Ws = sm + 128 * 65;      // 2 x [64][64]
    const int tid = threadIdx.x;
    const int row0 = blockIdx.x * 128;
    const int j0 = blockIdx.y * 2;
    const int j1 = j0 + 1;
    const bool has1 = (j1 < nmat);

    // load X tile (2048 float4 / 256 thr = 8 each), optional relu, zero-pad OOR rows
    {
        const float4* X4 = (const float4*)X;
#pragma unroll
        for (int i = 0; i < 8; ++i) {
            int id = i * 256 + tid;
            int r = id >> 4, k4 = id & 15;
            float4 v = make_float4(0.f, 0.f, 0.f, 0.f);
            if (row0 + r < N) v = X4[(size_t)(row0 + r) * 16 + k4];
            if (dorelu) {
                v.x = fmaxf(v.x, 0.f); v.y = fmaxf(v.y, 0.f);
                v.z = fmaxf(v.z, 0.f); v.w = fmaxf(v.w, 0.f);
            }
            float* dst = Xs + r * 65 + k4 * 4;
            dst[0] = v.x; dst[1] = v.y; dst[2] = v.z; dst[3] = v.w;
        }
    }
    // load the two weight mats (1024 float4 each / 256 thr = 4 each)
    {
        const float4* Wa = (const float4*)jobs.j[j0].W;
        const float4* Wb = (const float4*)jobs.j[has1 ? j1 : j0].W;
        float4* W0 = (float4*)Ws;
        float4* W1 = (float4*)(Ws + 4096);
#pragma unroll
        for (int i = 0; i < 4; ++i) {
            W0[i * 256 + tid] = Wa[i * 256 + tid];
            W1[i * 256 + tid] = Wb[i * 256 + tid];
        }
    }
    __syncthreads();

    const int tx = tid & 15;          // 16 col groups of 8 (0-7 -> mat0, 8-15 -> mat1)
    const int ty = tid >> 4;          // 16 row groups of 8
    const int mat = tx >> 3;
    const int cg = (tx & 7) * 8;
    const float* Wsel = Ws + mat * 4096;

    float acc[8][8];
#pragma unroll
    for (int i = 0; i < 8; ++i)
#pragma unroll
        for (int j = 0; j < 8; ++j) acc[i][j] = 0.f;

#pragma unroll 8
    for (int k = 0; k < 64; ++k) {
        float xf[8];
#pragma unroll
        for (int i = 0; i < 8; ++i) xf[i] = Xs[(ty * 8 + i) * 65 + k];
        float4 wa = *(const float4*)(Wsel + k * 64 + cg);
        float4 wb = *(const float4*)(Wsel + k * 64 + cg + 4);
        float wf[8] = {wa.x, wa.y, wa.z, wa.w, wb.x, wb.y, wb.z, wb.w};
#pragma unroll
        for (int i = 0; i < 8; ++i)
#pragma unroll
            for (int j = 0; j < 8; ++j) acc[i][j] += xf[i] * wf[j];
    }

    const bool valid = (mat == 0) || has1;
    const int js = (mat && has1) ? j1 : j0;
    const float* Bp = jobs.j[js].B;
    float* Op = jobs.j[js].O;
    if (valid) {
        float4 ba = *(const float4*)(Bp + cg);
        float4 bb = *(const float4*)(Bp + cg + 4);
        float bf[8] = {ba.x, ba.y, ba.z, ba.w, bb.x, bb.y, bb.z, bb.w};
#pragma unroll
        for (int i = 0; i < 8; ++i) {
            int r = row0 + ty * 8 + i;
            if (r < N) {
                float4 o0 = make_float4(acc[i][0] + bf[0], acc[i][1] + bf[1],
                                        acc[i][2] + bf[2], acc[i][3] + bf[3]);
                float4 o1 = make_float4(acc[i][4] + bf[4], acc[i][5] + bf[5],
                                        acc[i][6] + bf[6], acc[i][7] + bf[7]);
                float4* O4 = (float4*)(Op + (size_t)r * 64 + cg);
                O4[0] = o0; O4[1] = o1;
            }
        }
    }
}

// ---------------- sum skip weights over edge types sharing a dest ----------------
__global__ void sumskip(const float* __restrict__ Wl, const float* __restrict__ bl,
                        int t0, int t1, int t2, int t3, int cnt,
                        float* __restrict__ Wsum, float* __restrict__ bsum)
{
    int i = blockIdx.x * blockDim.x + threadIdx.x;
    int ts[4] = {t0, t1, t2, t3};
    if (i < 4096) {
        float s = 0.f;
        for (int j = 0; j < cnt; ++j) s += Wl[ts[j] * 4096 + i];
        Wsum[i] = s;
        if (i < 64) {
            float sb = 0.f;
            for (int j = 0; j < cnt; ++j) sb += bl[ts[j] * 64 + i];
            bsum[i] = sb;
        }
    }
}

// ---------------- softmax state init for all 9 types ----------------
__global__ void init_all(unsigned* __restrict__ mx, float* __restrict__ den, int total)
{
    int i = blockIdx.x * blockDim.x + threadIdx.x;
    if (i < total) { mx[i] = 0x007FFFFFu; den[i] = 0.f; }
}

// ---------------- pass A (all types): alpha + atomic segment max ----------------
__global__ void pass_a_all(const float* __restrict__ P,
                           const int* __restrict__ eidx, const float* __restrict__ eattr,
                           const float* __restrict__ WeL,
                           float* __restrict__ alpha, unsigned* __restrict__ gmax,
                           int NE, int N)
{
    const int t = blockIdx.y;
    const float* Q = P + (size_t)(t * 3 + 0) * PSTRIDE;
    const float* K = P + (size_t)(t * 3 + 1) * PSTRIDE;
    const int* src = eidx + (size_t)t * 2 * NE;
    const int* dst = src + NE;
    const float* eat = eattr + (size_t)t * NE * 2;
    float* alpha_t = alpha + (size_t)t * NE;
    unsigned* gmax_t = gmax + (size_t)t * N;

    __shared__ __align__(16) float sWe[128];
    int tid = threadIdx.x;
    if (tid < 128) sWe[tid] = WeL[t * 128 + tid];
    __syncthreads();

    int l16 = tid & 15;
    int e = blockIdx.x * (blockDim.x >> 4) + (tid >> 4);
    if (e >= NE) return;
    int s = src[e], d = dst[e];
    float2 ea = ((const float2*)eat)[e];
    float4 q = ((const float4*)Q)[d * 16 + l16];
    float4 k = ((const float4*)K)[s * 16 + l16];
    float4 w0 = ((const float4*)sWe)[l16];
    float4 w1 = ((const float4*)sWe)[16 + l16];
    float dotv = q.x * (k.x + ea.x * w0.x + ea.y * w1.x)
               + q.y * (k.y + ea.x * w0.y + ea.y * w1.y)
               + q.z * (k.z + ea.x * w0.z + ea.y * w1.z)
               + q.w * (k.w + ea.x * w0.w + ea.y * w1.w);
    unsigned hm = (tid & 16) ? 0xFFFF0000u : 0x0000FFFFu;
#pragma unroll
    for (int off = 8; off >= 1; off >>= 1)
        dotv += __shfl_down_sync(hm, dotv, off, 16);
    if (l16 == 0) {
        float a = dotv * 0.125f;
        alpha_t[e] = a;
        atomicMax(gmax_t + d, fenc(a));
    }
}

// ---------------- pass B (all types): exp + atomic denom ----------------
__global__ void pass_b_all(const float* __restrict__ alpha, const int* __restrict__ eidx,
                           const unsigned* __restrict__ gmax, float* __restrict__ wbuf,
                           float* __restrict__ den, int NE, int N)
{
    const int t = blockIdx.y;
    int e = blockIdx.x * blockDim.x + threadIdx.x;
    if (e >= NE) return;
    const int* dst = eidx + (size_t)t * 2 * NE + NE;
    int d = dst[e];
    float m = fdec(gmax[(size_t)t * N + d]);
    float w = __expf(alpha[(size_t)t * NE + e] - m);
    wbuf[(size_t)t * NE + e] = w;
    atomicAdd(den + (size_t)t * N + d, w);
}

// ---------------- pass C (all types): weighted scatter of V+e ----------------
__global__ void pass_c_all(const float* __restrict__ P,
                           const int* __restrict__ eidx, const float* __restrict__ eattr,
                           const float* __restrict__ WeL,
                           const float* __restrict__ wbuf, const float* __restrict__ den,
                           float* __restrict__ o1, float* __restrict__ o2, float* __restrict__ o3,
                           int NE, int N)
{
    const int t = blockIdx.y;
    const float* V = P + (size_t)(t * 3 + 2) * PSTRIDE;
    const int* src = eidx + (size_t)t * 2 * NE;
    const int* dst = src + NE;
    const float* eat = eattr + (size_t)t * NE * 2;
    const float* wb_t = wbuf + (size_t)t * NE;
    const float* den_t = den + (size_t)t * N;
    int di = c_dT[t] - 1;
    float* Out = (di == 0) ? o1 : (di == 1) ? o2 : o3;

    __shared__ __align__(16) float sWe[128];
    int tid = threadIdx.x;
    if (tid < 128) sWe[tid] = WeL[t * 128 + tid];
    __syncthreads();

    int l16 = tid & 15;
    int e = blockIdx.x * (blockDim.x >> 4) + (tid >> 4);
    if (e >= NE) return;
    int s = src[e], d = dst[e];
    float coef = wb_t[e] / (den_t[d] + 1e-16f);
    float2 ea = ((const float2*)eat)[e];
    float4 v = ((const float4*)V)[s * 16 + l16];
    float4 w0 = ((const float4*)sWe)[l16];
    float4 w1 = ((const float4*)sWe)[16 + l16];
    float rx = coef * (v.x + ea.x * w0.x + ea.y * w1.x);
    float ry = coef * (v.y + ea.x * w0.y + ea.y * w1.y);
    float rz = coef * (v.z + ea.x * w0.z + ea.y * w1.z);
    float rw = coef * (v.w + ea.x * w0.w + ea.y * w1.w);
    float* p = Out + (size_t)d * 64 + l16 * 4;
    asm volatile("red.global.add.v4.f32 [%0], {%1,%2,%3,%4};"
                 :: "l"(p), "f"(rx), "f"(ry), "f"(rz), "f"(rw) : "memory");
}

// ---------------- final linear (with fused relu on input) ----------------
__global__ void final_lin(const float* __restrict__ X, const float* __restrict__ W,
                          const float* __restrict__ b, float* __restrict__ out, int N)
{
    __shared__ float sW[256];
    int tid = threadIdx.x;
    if (tid < 256) sW[tid] = W[tid];
    __syncthreads();
    int warp = tid >> 5, lane = tid & 31;
    int row = blockIdx.x * 8 + warp;
    if (row >= N) return;
    float2 x2 = ((const float2*)(X + (size_t)row * 64))[lane];
    x2.x = fmaxf(x2.x, 0.f); x2.y = fmaxf(x2.y, 0.f);
    float a0 = x2.x * sW[(2 * lane) * 4 + 0] + x2.y * sW[(2 * lane + 1) * 4 + 0];
    float a1 = x2.x * sW[(2 * lane) * 4 + 1] + x2.y * sW[(2 * lane + 1) * 4 + 1];
    float a2 = x2.x * sW[(2 * lane) * 4 + 2] + x2.y * sW[(2 * lane + 1) * 4 + 2];
    float a3 = x2.x * sW[(2 * lane) * 4 + 3] + x2.y * sW[(2 * lane + 1) * 4 + 3];
#pragma unroll
    for (int off = 16; off >= 1; off >>= 1) {
        a0 += __shfl_down_sync(0xffffffffu, a0, off);
        a1 += __shfl_down_sync(0xffffffffu, a1, off);
        a2 += __shfl_down_sync(0xffffffffu, a2, off);
        a3 += __shfl_down_sync(0xffffffffu, a3, off);
    }
    if (lane == 0) {
        float4 o = make_float4(a0 + b[0], a1 + b[1], a2 + b[2], a3 + b[3]);
        ((float4*)out)[row] = o;
    }
}

// ---------------- host driver ----------------
extern "C" void kernel_launch(void* const* d_in, const int* in_sizes, int n_in,
                              void* d_out, int out_size)
{
    const float* xin[4] = {(const float*)d_in[0], (const float*)d_in[1],
                           (const float*)d_in[2], (const float*)d_in[3]};
    const int*   eidx  = (const int*)d_in[4];
    const float* eattr = (const float*)d_in[5];
    const float* Wq = (const float*)d_in[6];  const float* bq = (const float*)d_in[7];
    const float* Wk = (const float*)d_in[8];  const float* bk = (const float*)d_in[9];
    const float* Wv = (const float*)d_in[10]; const float* bv = (const float*)d_in[11];
    const float* We = (const float*)d_in[12];
    const float* Wsk = (const float*)d_in[13]; const float* bsk = (const float*)d_in[14];
    const float* linW = (const float*)d_in[15]; const float* linb = (const float*)d_in[16];

    const int N  = in_sizes[0] / HH;
    const int NE = in_sizes[5] / (TT * 2);

    float *pP, *pA, *pWb, *pD, *pWs, *pBs;
    float *pOa[3], *pOb[3];
    unsigned* pM;
    cudaGetSymbolAddress((void**)&pP, g_P);
    cudaGetSymbolAddress((void**)&pOa[0], g_outA); pOa[1] = pOa[0] + NMAX * HH; pOa[2] = pOa[1] + NMAX * HH;
    cudaGetSymbolAddress((void**)&pOb[0], g_outB); pOb[1] = pOb[0] + NMAX * HH; pOb[2] = pOb[1] + NMAX * HH;
    cudaGetSymbolAddress((void**)&pA, g_alpha);
    cudaGetSymbolAddress((void**)&pWb, g_wbuf);
    cudaGetSymbolAddress((void**)&pM, g_mx);
    cudaGetSymbolAddress((void**)&pD, g_den);
    cudaGetSymbolAddress((void**)&pWs, g_Wsum);
    cudaGetSymbolAddress((void**)&pBs, g_bsum);

    cudaFuncSetAttribute(gemm_multi, cudaFuncAttributeMaxDynamicSharedMemorySize, GM_SMEM);

    const int rowTiles = (N + 127) / 128;

    for (int l = 0; l < 2; ++l) {
        const float* xc[4];
        float** pO;
        int dorelu;
        if (l == 0) { xc[0] = xin[0]; xc[1] = xin[1]; xc[2] = xin[2]; xc[3] = xin[3]; pO = pOa; dorelu = 0; }
        else        { xc[0] = xin[0]; xc[1] = pOa[0]; xc[2] = pOa[1]; xc[3] = pOa[2]; pO = pOb; dorelu = 1; }

        const int wb = l * TT;
        const float* Wsl = Wsk + (size_t)wb * 4096;
        const float* bsl = bsk + (size_t)wb * 64;

        // summed skip weights per dest type
        sumskip<<<16, 256>>>(Wsl, bsl, 0, 5, 0, 0, 2, pWs + 0 * 4096, pBs + 0 * 64);
        sumskip<<<16, 256>>>(Wsl, bsl, 1, 3, 7, 0, 3, pWs + 1 * 4096, pBs + 1 * 64);
        sumskip<<<16, 256>>>(Wsl, bsl, 2, 4, 6, 8, 4, pWs + 2 * 4096, pBs + 2 * 64);

        // helper lambdas for job construction
        auto WQ = [&](int t){ return Wq + (size_t)(wb + t) * 4096; };
        auto BQ = [&](int t){ return bq + (size_t)(wb + t) * 64; };
        auto WK = [&](int t){ return Wk + (size_t)(wb + t) * 4096; };
        auto BK = [&](int t){ return bk + (size_t)(wb + t) * 64; };
        auto WV = [&](int t){ return Wv + (size_t)(wb + t) * 4096; };
        auto BV = [&](int t){ return bv + (size_t)(wb + t) * 64; };
        auto PP = [&](int t, int role){ return pP + (size_t)(t * 3 + role) * PSTRIDE; };

        // x0 (SB): K/V for t=0,1,2   (never relu'd: xs[0] stays x_SB)
        {
            Jobs J{};
            int n = 0;
            for (int t = 0; t <= 2; ++t) {
                J.j[n++] = {WK(t), BK(t), PP(t, 1)};
                J.j[n++] = {WV(t), BV(t), PP(t, 2)};
            }
            gemm_multi<<<dim3(rowTiles, (n + 1) / 2), 256, GM_SMEM>>>(xc[0], J, n, N, 0);
        }
        // x1 (PV): K/V t=3,4,5; Q t=0,5; skip d1
        {
            Jobs J{};
            int n = 0;
            for (int t = 3; t <= 5; ++t) {
                J.j[n++] = {WK(t), BK(t), PP(t, 1)};
                J.j[n++] = {WV(t), BV(t), PP(t, 2)};
            }
            J.j[n++] = {WQ(0), BQ(0), PP(0, 0)};
            J.j[n++] = {WQ(5), BQ(5), PP(5, 0)};
            J.j[n++] = {pWs + 0 * 4096, pBs + 0 * 64, pO[0]};
            gemm_multi<<<dim3(rowTiles, (n + 1) / 2), 256, GM_SMEM>>>(xc[1], J, n, N, dorelu);
        }
        // x2 (PQ): K/V t=6,7; Q t=1,3,7; skip d2
        {
            Jobs J{};
            int n = 0;
            for (int t = 6; t <= 7; ++t) {
                J.j[n++] = {WK(t), BK(t), PP(t, 1)};
                J.j[n++] = {WV(t), BV(t), PP(t, 2)};
            }
            J.j[n++] = {WQ(1), BQ(1), PP(1, 0)};
            J.j[n++] = {WQ(3), BQ(3), PP(3, 0)};
            J.j[n++] = {WQ(7), BQ(7), PP(7, 0)};
            J.j[n++] = {pWs + 1 * 4096, pBs + 1 * 64, pO[1]};
            gemm_multi<<<dim3(rowTiles, (n + 1) / 2), 256, GM_SMEM>>>(xc[2], J, n, N, dorelu);
        }
        // x3 (NB): K/V t=8; Q t=2,4,6,8; skip d3
        {
            Jobs J{};
            int n = 0;
            J.j[n++] = {WK(8), BK(8), PP(8, 1)};
            J.j[n++] = {WV(8), BV(8), PP(8, 2)};
            J.j[n++] = {WQ(2), BQ(2), PP(2, 0)};
            J.j[n++] = {WQ(4), BQ(4), PP(4, 0)};
            J.j[n++] = {WQ(6), BQ(6), PP(6, 0)};
            J.j[n++] = {WQ(8), BQ(8), PP(8, 0)};
            J.j[n++] = {pWs + 2 * 4096, pBs + 2 * 64, pO[2]};
            gemm_multi<<<dim3(rowTiles, (n + 1) / 2), 256, GM_SMEM>>>(xc[3], J, n, N, dorelu);
        }

        // edge passes, all 9 types batched
        init_all<<<(9 * N + 255) / 256, 256>>>(pM, pD, 9 * N);
        const float* WeL = We + (size_t)wb * 128;
        pass_a_all<<<dim3((NE + 15) / 16, 9), 256>>>(pP, eidx, eattr, WeL, pA, pM, NE, N);
        pass_b_all<<<dim3((NE + 255) / 256, 9), 256>>>(pA, eidx, pM, pWb, pD, NE, N);
        pass_c_all<<<dim3((NE + 15) / 16, 9), 256>>>(pP, eidx, eattr, WeL, pWb, pD,
                                                     pO[0], pO[1], pO[2], NE, N);
    }

    // final linear on relu(PQ) (dest index 2 -> pOb[1])
    final_lin<<<(N + 7) / 8, 256>>>(pOb[1], linW, linb, (float*)d_out, N);
}

// round 3
// speedup vs baseline: 1.2690x; 1.1446x over previous
#include <cuda_runtime.h>
#include <cstdint>

#define HH 64
#define TT 9
#define NMAX 50048
#define NEMAX 250016
#define PSTRIDE ((size_t)NMAX * HH)

// ---------------- scratch (device globals; bss, no runtime allocation) ----------------
__device__ __align__(256) float g_P[27 * PSTRIDE];     // projections: idx = t*3+role (0=Q,1=K,2=V)
__device__ __align__(256) float g_outA[3][NMAX * HH];  // layer-1 node outputs (pre-relu)
__device__ __align__(256) float g_outB[3][NMAX * HH];  // layer-2 node outputs (pre-relu)
__device__ __align__(256) int    g_cnt[9 * NMAX];
__device__ __align__(256) int    g_cur[9 * NMAX];
__device__ __align__(256) int    g_rp[9 * (NMAX + 1)];
__device__ __align__(256) int    g_srcp[9 * (size_t)NEMAX];
__device__ __align__(256) float2 g_eap[9 * (size_t)NEMAX];
__device__ __align__(256) float g_Wsum[3 * 4096];
__device__ __align__(256) float g_bsum[3 * 64];

__constant__ int c_dT[9] = {1, 2, 3, 2, 3, 1, 3, 2, 3};

// ---------------- multi-weight GEMM ----------------
// Out_j[N,64] = X[N,64] @ W_j[64,64] + B_j  for up to 10 weight matrices.
// Block: 256 threads, 128 rows x 128 cols (2 weight mats), 8x8 per thread.
struct Job { const float* W; const float* B; float* O; };
struct Jobs { Job j[10]; };

#define XS_STRIDE 68
#define GM_SMEM ((128 * XS_STRIDE + 2 * 64 * 64) * 4)

__global__ void __launch_bounds__(256, 2) gemm_multi(
    const float* __restrict__ X, Jobs jobs, int nmat, int N, int dorelu)
{
    extern __shared__ float sm[];
    float* Xs = sm;                        // [128][68] padded (16B-aligned rows)
    float* Ws = sm + 128 * XS_STRIDE;      // 2 x [64][64]
    const int tid = threadIdx.x;
    const int row0 = blockIdx.x * 128;
    const int j0 = blockIdx.y * 2;
    const int j1 = j0 + 1;
    const bool has1 = (j1 < nmat);

    // load X tile (2048 float4 / 256 thr = 8 each), optional relu, zero-pad OOR rows
    {
        const float4* X4 = (const float4*)X;
#pragma unroll
        for (int i = 0; i < 8; ++i) {
            int id = i * 256 + tid;
            int r = id >> 4, k4 = id & 15;
            float4 v = make_float4(0.f, 0.f, 0.f, 0.f);
            if (row0 + r < N) v = X4[(size_t)(row0 + r) * 16 + k4];
            if (dorelu) {
                v.x = fmaxf(v.x, 0.f); v.y = fmaxf(v.y, 0.f);
                v.z = fmaxf(v.z, 0.f); v.w = fmaxf(v.w, 0.f);
            }
            *(float4*)(Xs + r * XS_STRIDE + k4 * 4) = v;
        }
    }
    // load the two weight mats (1024 float4 each / 256 thr = 4 each)
    {
        const float4* Wa = (const float4*)jobs.j[j0].W;
        const float4* Wb = (const float4*)jobs.j[has1 ? j1 : j0].W;
        float4* W0 = (float4*)Ws;
        float4* W1 = (float4*)(Ws + 4096);
#pragma unroll
        for (int i = 0; i < 4; ++i) {
            W0[i * 256 + tid] = Wa[i * 256 + tid];
            W1[i * 256 + tid] = Wb[i * 256 + tid];
        }
    }
    __syncthreads();

    const int tx = tid & 15;          // 16 col groups of 8 (0-7 -> mat0, 8-15 -> mat1)
    const int ty = tid >> 4;          // 16 row groups of 8
    const int mat = tx >> 3;
    const int cg = (tx & 7) * 8;
    const float* Wsel = Ws + mat * 4096;
    const float* Xrow = Xs + ty * 8 * XS_STRIDE;

    float acc[8][8];
#pragma unroll
    for (int i = 0; i < 8; ++i)
#pragma unroll
        for (int j = 0; j < 8; ++j) acc[i][j] = 0.f;

#pragma unroll
    for (int k0 = 0; k0 < 64; k0 += 4) {
        float4 xr[8];
#pragma unroll
        for (int i = 0; i < 8; ++i)
            xr[i] = *(const float4*)(Xrow + i * XS_STRIDE + k0);
#pragma unroll
        for (int kk = 0; kk < 4; ++kk) {
            float4 wa = *(const float4*)(Wsel + (k0 + kk) * 64 + cg);
            float4 wb = *(const float4*)(Wsel + (k0 + kk) * 64 + cg + 4);
            float wf[8] = {wa.x, wa.y, wa.z, wa.w, wb.x, wb.y, wb.z, wb.w};
#pragma unroll
            for (int i = 0; i < 8; ++i) {
                float xv = (kk == 0) ? xr[i].x : (kk == 1) ? xr[i].y : (kk == 2) ? xr[i].z : xr[i].w;
#pragma unroll
                for (int j = 0; j < 8; ++j) acc[i][j] += xv * wf[j];
            }
        }
    }

    const bool valid = (mat == 0) || has1;
    const int js = (mat && has1) ? j1 : j0;
    const float* Bp = jobs.j[js].B;
    float* Op = jobs.j[js].O;
    if (valid) {
        float4 ba = *(const float4*)(Bp + cg);
        float4 bb = *(const float4*)(Bp + cg + 4);
        float bf[8] = {ba.x, ba.y, ba.z, ba.w, bb.x, bb.y, bb.z, bb.w};
#pragma unroll
        for (int i = 0; i < 8; ++i) {
            int r = row0 + ty * 8 + i;
            if (r < N) {
                float4 o0 = make_float4(acc[i][0] + bf[0], acc[i][1] + bf[1],
                                        acc[i][2] + bf[2], acc[i][3] + bf[3]);
                float4 o1 = make_float4(acc[i][4] + bf[4], acc[i][5] + bf[5],
                                        acc[i][6] + bf[6], acc[i][7] + bf[7]);
                float4* O4 = (float4*)(Op + (size_t)r * 64 + cg);
                O4[0] = o0; O4[1] = o1;
            }
        }
    }
}

// ---------------- sum skip weights over edge types sharing a dest ----------------
__global__ void sumskip(const float* __restrict__ Wl, const float* __restrict__ bl,
                        int t0, int t1, int t2, int t3, int cnt,
                        float* __restrict__ Wsum, float* __restrict__ bsum)
{
    int i = blockIdx.x * blockDim.x + threadIdx.x;
    int ts[4] = {t0, t1, t2, t3};
    if (i < 4096) {
        float s = 0.f;
        for (int j = 0; j < cnt; ++j) s += Wl[ts[j] * 4096 + i];
        Wsum[i] = s;
        if (i < 64) {
            float sb = 0.f;
            for (int j = 0; j < cnt; ++j) sb += bl[ts[j] * 64 + i];
            bsum[i] = sb;
        }
    }
}

// ---------------- CSR build ----------------
__global__ void zero_cnt(int* __restrict__ cnt, int total)
{
    int i = blockIdx.x * blockDim.x + threadIdx.x;
    if (i < total) cnt[i] = 0;
}

__global__ void count_deg(const int* __restrict__ eidx, int* __restrict__ cnt, int NE)
{
    int t = blockIdx.y;
    int e = blockIdx.x * blockDim.x + threadIdx.x;
    if (e >= NE) return;
    int d = eidx[(size_t)t * 2 * NE + NE + e];
    atomicAdd(&cnt[t * NMAX + d], 1);
}

// per-type exclusive scan: 1 block of 1024 threads per type (grid.y)
__global__ void scan_deg(const int* __restrict__ cnt, int* __restrict__ rp,
                         int* __restrict__ cur, int N, int NE)
{
    int t = blockIdx.y;
    int tid = threadIdx.x;
    __shared__ int sh[1024];
    __shared__ int s_carry;
    if (tid == 0) s_carry = 0;
    __syncthreads();
    for (int base = 0; base < N; base += 1024) {
        int i = base + tid;
        int v = (i < N) ? cnt[t * NMAX + i] : 0;
        sh[tid] = v;
        __syncthreads();
#pragma unroll
        for (int off = 1; off < 1024; off <<= 1) {
            int x = (tid >= off) ? sh[tid - off] : 0;
            __syncthreads();
            sh[tid] += x;
            __syncthreads();
        }
        int incl = sh[tid];
        int excl = incl - v;
        int c = s_carry;
        if (i < N) {
            rp[t * (NMAX + 1) + i] = c + excl;
            cur[t * NMAX + i] = c + excl;
        }
        __syncthreads();
        if (tid == 1023) s_carry = c + incl;
        __syncthreads();
    }
    if (tid == 0) rp[t * (NMAX + 1) + N] = NE;
}

__global__ void place_edges(const int* __restrict__ eidx, const float* __restrict__ eattr,
                            int* __restrict__ cur, int* __restrict__ srcp,
                            float2* __restrict__ eap, int NE)
{
    int t = blockIdx.y;
    int e = blockIdx.x * blockDim.x + threadIdx.x;
    if (e >= NE) return;
    const int* src = eidx + (size_t)t * 2 * NE;
    const int* dst = src + NE;
    int d = dst[e];
    int s = src[e];
    float2 ea = ((const float2*)(eattr + (size_t)t * NE * 2))[e];
    int pos = atomicAdd(&cur[t * NMAX + d], 1);
    srcp[(size_t)t * NEMAX + pos] = s;
    eap[(size_t)t * NEMAX + pos] = ea;
}

// ---------------- fused edge kernel: warp per destination, online softmax ----------------
// lanes each own 2 consecutive feature floats.
__global__ void __launch_bounds__(256) edge_fused(
    const float* __restrict__ P, const int* __restrict__ rp,
    const int* __restrict__ srcp, const float2* __restrict__ eap,
    const float* __restrict__ WeL,
    float* __restrict__ o1, float* __restrict__ o2, float* __restrict__ o3,
    int N)
{
    const int t = blockIdx.y;
    const float2* Q2 = (const float2*)(P + (size_t)(t * 3 + 0) * PSTRIDE);
    const float2* K2 = (const float2*)(P + (size_t)(t * 3 + 1) * PSTRIDE);
    const float2* V2 = (const float2*)(P + (size_t)(t * 3 + 2) * PSTRIDE);
    const int* sp = srcp + (size_t)t * NEMAX;
    const float2* ep = eap + (size_t)t * NEMAX;
    const int di = c_dT[t] - 1;
    float* Out = (di == 0) ? o1 : (di == 1) ? o2 : o3;

    const int warp = threadIdx.x >> 5;
    const int lane = threadIdx.x & 31;
    const int d = blockIdx.x * 8 + warp;
    if (d >= N) return;

    const int beg = rp[t * (NMAX + 1) + d];
    const int end = rp[t * (NMAX + 1) + d + 1];
    if (beg == end) return;

    // We rows (2 x 64) as per-lane float2
    const float2 w0 = ((const float2*)(WeL + t * 128))[lane];
    const float2 w1 = ((const float2*)(WeL + t * 128 + 64))[lane];
    const float2 q = Q2[(size_t)d * 32 + lane];

    float m = -3.4e38f, den = 0.f, accx = 0.f, accy = 0.f;

    int j = beg;
    int s = sp[j];
    float2 ea = ep[j];
    float2 k2 = K2[(size_t)s * 32 + lane];
    float2 v2 = V2[(size_t)s * 32 + lane];

    while (j < end) {
        float2 e2 = make_float2(ea.x * w0.x + ea.y * w1.x,
                                ea.x * w0.y + ea.y * w1.y);
        float part = q.x * (k2.x + e2.x) + q.y * (k2.y + e2.y);
        float vx = v2.x + e2.x, vy = v2.y + e2.y;

        // prefetch next edge while reducing
        int jn = j + 1;
        int sn = 0; float2 ean, k2n, v2n;
        if (jn < end) {
            sn = sp[jn];
            ean = ep[jn];
            k2n = K2[(size_t)sn * 32 + lane];
            v2n = V2[(size_t)sn * 32 + lane];
        }

#pragma unroll
        for (int off = 16; off >= 1; off >>= 1)
            part += __shfl_xor_sync(0xffffffffu, part, off);
        float a = part * 0.125f;

        if (a > m) {
            float f = __expf(m - a);
            den *= f; accx *= f; accy *= f;
            m = a;
        }
        float w = __expf(a - m);
        den += w;
        accx += w * vx;
        accy += w * vy;

        j = jn; s = sn; ea = ean; k2 = k2n; v2 = v2n;
    }

    float inv = 1.f / (den + 1e-16f);
    float* p = Out + (size_t)d * 64 + lane * 2;
    float rx = accx * inv, ry = accy * inv;
    asm volatile("red.global.add.v2.f32 [%0], {%1,%2};"
                 :: "l"(p), "f"(rx), "f"(ry) : "memory");
}

// ---------------- final linear (with fused relu on input) ----------------
__global__ void final_lin(const float* __restrict__ X, const float* __restrict__ W,
                          const float* __restrict__ b, float* __restrict__ out, int N)
{
    __shared__ float sW[256];
    int tid = threadIdx.x;
    if (tid < 256) sW[tid] = W[tid];
    __syncthreads();
    int warp = tid >> 5, lane = tid & 31;
    int row = blockIdx.x * 8 + warp;
    if (row >= N) return;
    float2 x2 = ((const float2*)(X + (size_t)row * 64))[lane];
    x2.x = fmaxf(x2.x, 0.f); x2.y = fmaxf(x2.y, 0.f);
    float a0 = x2.x * sW[(2 * lane) * 4 + 0] + x2.y * sW[(2 * lane + 1) * 4 + 0];
    float a1 = x2.x * sW[(2 * lane) * 4 + 1] + x2.y * sW[(2 * lane + 1) * 4 + 1];
    float a2 = x2.x * sW[(2 * lane) * 4 + 2] + x2.y * sW[(2 * lane + 1) * 4 + 2];
    float a3 = x2.x * sW[(2 * lane) * 4 + 3] + x2.y * sW[(2 * lane + 1) * 4 + 3];
#pragma unroll
    for (int off = 16; off >= 1; off >>= 1) {
        a0 += __shfl_down_sync(0xffffffffu, a0, off);
        a1 += __shfl_down_sync(0xffffffffu, a1, off);
        a2 += __shfl_down_sync(0xffffffffu, a2, off);
        a3 += __shfl_down_sync(0xffffffffu, a3, off);
    }
    if (lane == 0) {
        float4 o = make_float4(a0 + b[0], a1 + b[1], a2 + b[2], a3 + b[3]);
        ((float4*)out)[row] = o;
    }
}

// ---------------- host driver ----------------
extern "C" void kernel_launch(void* const* d_in, const int* in_sizes, int n_in,
                              void* d_out, int out_size)
{
    const float* xin[4] = {(const float*)d_in[0], (const float*)d_in[1],
                           (const float*)d_in[2], (const float*)d_in[3]};
    const int*   eidx  = (const int*)d_in[4];
    const float* eattr = (const float*)d_in[5];
    const float* Wq = (const float*)d_in[6];  const float* bq = (const float*)d_in[7];
    const float* Wk = (const float*)d_in[8];  const float* bk = (const float*)d_in[9];
    const float* Wv = (const float*)d_in[10]; const float* bv = (const float*)d_in[11];
    const float* We = (const float*)d_in[12];
    const float* Wsk = (const float*)d_in[13]; const float* bsk = (const float*)d_in[14];
    const float* linW = (const float*)d_in[15]; const float* linb = (const float*)d_in[16];

    const int N  = in_sizes[0] / HH;
    const int NE = in_sizes[5] / (TT * 2);

    float *pP, *pWs, *pBs;
    float *pOa[3], *pOb[3];
    int *pCnt, *pCur, *pRp, *pSrcp;
    float2* pEap;
    cudaGetSymbolAddress((void**)&pP, g_P);
    cudaGetSymbolAddress((void**)&pOa[0], g_outA); pOa[1] = pOa[0] + NMAX * HH; pOa[2] = pOa[1] + NMAX * HH;
    cudaGetSymbolAddress((void**)&pOb[0], g_outB); pOb[1] = pOb[0] + NMAX * HH; pOb[2] = pOb[1] + NMAX * HH;
    cudaGetSymbolAddress((void**)&pCnt, g_cnt);
    cudaGetSymbolAddress((void**)&pCur, g_cur);
    cudaGetSymbolAddress((void**)&pRp, g_rp);
    cudaGetSymbolAddress((void**)&pSrcp, g_srcp);
    cudaGetSymbolAddress((void**)&pEap, g_eap);
    cudaGetSymbolAddress((void**)&pWs, g_Wsum);
    cudaGetSymbolAddress((void**)&pBs, g_bsum);

    cudaFuncSetAttribute(gemm_multi, cudaFuncAttributeMaxDynamicSharedMemorySize, GM_SMEM);

    const int rowTiles = (N + 127) / 128;

    // ---- CSR build (graph static for the whole call) ----
    zero_cnt<<<(9 * NMAX + 255) / 256, 256>>>(pCnt, 9 * NMAX);
    count_deg<<<dim3((NE + 255) / 256, 9), 256>>>(eidx, pCnt, NE);
    scan_deg<<<dim3(1, 9), 1024>>>(pCnt, pRp, pCur, N, NE);
    place_edges<<<dim3((NE + 255) / 256, 9), 256>>>(eidx, eattr, pCur, pSrcp, pEap, NE);

    for (int l = 0; l < 2; ++l) {
        const float* xc[4];
        float** pO;
        int dorelu;
        if (l == 0) { xc[0] = xin[0]; xc[1] = xin[1]; xc[2] = xin[2]; xc[3] = xin[3]; pO = pOa; dorelu = 0; }
        else        { xc[0] = xin[0]; xc[1] = pOa[0]; xc[2] = pOa[1]; xc[3] = pOa[2]; pO = pOb; dorelu = 1; }

        const int wb = l * TT;
        const float* Wsl = Wsk + (size_t)wb * 4096;
        const float* bsl = bsk + (size_t)wb * 64;

        sumskip<<<16, 256>>>(Wsl, bsl, 0, 5, 0, 0, 2, pWs + 0 * 4096, pBs + 0 * 64);
        sumskip<<<16, 256>>>(Wsl, bsl, 1, 3, 7, 0, 3, pWs + 1 * 4096, pBs + 1 * 64);
        sumskip<<<16, 256>>>(Wsl, bsl, 2, 4, 6, 8, 4, pWs + 2 * 4096, pBs + 2 * 64);

        auto WQ = [&](int t){ return Wq + (size_t)(wb + t) * 4096; };
        auto BQ = [&](int t){ return bq + (size_t)(wb + t) * 64; };
        auto WK = [&](int t){ return Wk + (size_t)(wb + t) * 4096; };
        auto BK = [&](int t){ return bk + (size_t)(wb + t) * 64; };
        auto WV = [&](int t){ return Wv + (size_t)(wb + t) * 4096; };
        auto BV = [&](int t){ return bv + (size_t)(wb + t) * 64; };
        auto PP = [&](int t, int role){ return pP + (size_t)(t * 3 + role) * PSTRIDE; };

        // x0 (SB): K/V for t=0,1,2  (xs[0] is never updated/relu'd)
        {
            Jobs J{}; int n = 0;
            for (int t = 0; t <= 2; ++t) {
                J.j[n++] = {WK(t), BK(t), PP(t, 1)};
                J.j[n++] = {WV(t), BV(t), PP(t, 2)};
            }
            gemm_multi<<<dim3(rowTiles, (n + 1) / 2), 256, GM_SMEM>>>(xc[0], J, n, N, 0);
        }
        // x1 (PV): K/V t=3,4,5; Q t=0,5; skip d1
        {
            Jobs J{}; int n = 0;
            for (int t = 3; t <= 5; ++t) {
                J.j[n++] = {WK(t), BK(t), PP(t, 1)};
                J.j[n++] = {WV(t), BV(t), PP(t, 2)};
            }
            J.j[n++] = {WQ(0), BQ(0), PP(0, 0)};
            J.j[n++] = {WQ(5), BQ(5), PP(5, 0)};
            J.j[n++] = {pWs + 0 * 4096, pBs + 0 * 64, pO[0]};
            gemm_multi<<<dim3(rowTiles, (n + 1) / 2), 256, GM_SMEM>>>(xc[1], J, n, N, dorelu);
        }
        // x2 (PQ): K/V t=6,7; Q t=1,3,7; skip d2
        {
            Jobs J{}; int n = 0;
            for (int t = 6; t <= 7; ++t) {
                J.j[n++] = {WK(t), BK(t), PP(t, 1)};
                J.j[n++] = {WV(t), BV(t), PP(t, 2)};
            }
            J.j[n++] = {WQ(1), BQ(1), PP(1, 0)};
            J.j[n++] = {WQ(3), BQ(3), PP(3, 0)};
            J.j[n++] = {WQ(7), BQ(7), PP(7, 0)};
            J.j[n++] = {pWs + 1 * 4096, pBs + 1 * 64, pO[1]};
            gemm_multi<<<dim3(rowTiles, (n + 1) / 2), 256, GM_SMEM>>>(xc[2], J, n, N, dorelu);
        }
        // x3 (NB): K/V t=8; Q t=2,4,6,8; skip d3
        {
            Jobs J{}; int n = 0;
            J.j[n++] = {WK(8), BK(8), PP(8, 1)};
            J.j[n++] = {WV(8), BV(8), PP(8, 2)};
            J.j[n++] = {WQ(2), BQ(2), PP(2, 0)};
            J.j[n++] = {WQ(4), BQ(4), PP(4, 0)};
            J.j[n++] = {WQ(6), BQ(6), PP(6, 0)};
            J.j[n++] = {WQ(8), BQ(8), PP(8, 0)};
            J.j[n++] = {pWs + 2 * 4096, pBs + 2 * 64, pO[2]};
            gemm_multi<<<dim3(rowTiles, (n + 1) / 2), 256, GM_SMEM>>>(xc[3], J, n, N, dorelu);
        }

        // fused edge aggregation, all 9 types
        const float* WeL = We + (size_t)wb * 128;
        edge_fused<<<dim3((N + 7) / 8, 9), 256>>>(pP, pRp, pSrcp, pEap, WeL,
                                                  pO[0], pO[1], pO[2], N);
    }

    // final linear on relu(PQ) (dest index 2 -> pOb[1])
    final_lin<<<(N + 7) / 8, 256>>>(pOb[1], linW, linb, (float*)d_out, N);
}

// round 4
// speedup vs baseline: 1.3080x; 1.0307x over previous
#include <cuda_runtime.h>
#include <cstdint>

#define HH 64
#define TT 9
#define NMAX 50048
#define NEMAX 250016
#define PSTRIDE ((size_t)NMAX * HH)

// ---------------- scratch (device globals; bss, no runtime allocation) ----------------
__device__ __align__(256) float g_P[27 * PSTRIDE];     // projections: idx = t*3+role (0=Q,1=K,2=V)
__device__ __align__(256) float g_outA[3][NMAX * HH];  // layer-1 node outputs (pre-relu)
__device__ __align__(256) float g_outB[3][NMAX * HH];  // layer-2 node outputs (pre-relu)
__device__ __align__(256) int    g_cnt[9 * NMAX];
__device__ __align__(256) int    g_cur[9 * NMAX];
__device__ __align__(256) int    g_rpb[9 * NMAX];
__device__ __align__(256) float4 g_er[9 * (size_t)NEMAX];   // {src_bits, ex, ey, pad}
__device__ __align__(256) int    g_cursor[9];
__device__ __align__(256) float g_Wsum[3 * 4096];
__device__ __align__(256) float g_bsum[3 * 64];

__constant__ int c_dT[9] = {1, 2, 3, 2, 3, 1, 3, 2, 3};

// ---------------- multi-weight GEMM via tensor cores (tf32, 3-way split) ----------------
// Out_j[N,64] = X[N,64] @ W_j[64,64] + B_j  for up to 10 weight matrices.
// Block: 256 threads (8 warps), 128 rows x 2 mats. Warp w: mat=w&1, rows 32*(w>>2? no: w>>1)
struct Job { const float* W; const float* B; float* O; };
struct Jobs { Job j[10]; };

#define XS_STRIDE 68
#define WT_STRIDE 68
#define GM_SMEM ((128 * XS_STRIDE + 2 * 64 * WT_STRIDE) * 4)

__device__ __forceinline__ void mma_tf32(float* d, const unsigned* a, unsigned b0, unsigned b1)
{
    asm volatile(
        "mma.sync.aligned.m16n8k8.row.col.f32.tf32.tf32.f32 "
        "{%0,%1,%2,%3}, {%4,%5,%6,%7}, {%8,%9}, {%0,%1,%2,%3};"
        : "+f"(d[0]), "+f"(d[1]), "+f"(d[2]), "+f"(d[3])
        : "r"(a[0]), "r"(a[1]), "r"(a[2]), "r"(a[3]), "r"(b0), "r"(b1));
}
__device__ __forceinline__ void split_tf32(float x, unsigned& hi, unsigned& lo)
{
    unsigned hx = __float_as_uint(x) & 0xFFFFE000u;
    hi = hx;
    lo = __float_as_uint(x - __uint_as_float(hx));
}

__global__ void __launch_bounds__(256, 2) gemm_mma(
    const float* __restrict__ X, Jobs jobs, int nmat, int N, int dorelu)
{
    extern __shared__ float sm[];
    float* Xs = sm;                          // [128][68]
    float* Wt = sm + 128 * XS_STRIDE;        // 2 x [64][68], transposed: Wt[n][k]
    const int tid = threadIdx.x;
    const int row0 = blockIdx.x * 128;
    const int j0 = blockIdx.y * 2;
    const int j1 = j0 + 1;
    const bool has1 = (j1 < nmat);

    // load X tile (2048 float4 / 256 thr = 8 each), optional relu, zero-pad OOR rows
    {
        const float4* X4 = (const float4*)X;
#pragma unroll
        for (int i = 0; i < 8; ++i) {
            int id = i * 256 + tid;
            int r = id >> 4, k4 = id & 15;
            float4 v = make_float4(0.f, 0.f, 0.f, 0.f);
            if (row0 + r < N) v = X4[(size_t)(row0 + r) * 16 + k4];
            if (dorelu) {
                v.x = fmaxf(v.x, 0.f); v.y = fmaxf(v.y, 0.f);
                v.z = fmaxf(v.z, 0.f); v.w = fmaxf(v.w, 0.f);
            }
            *(float4*)(Xs + r * XS_STRIDE + k4 * 4) = v;
        }
    }
    // load + transpose the two weight mats: W[k][n] (row-major) -> Wt[n][k]
    {
        const float4* Wa = (const float4*)jobs.j[j0].W;
        const float4* Wb = (const float4*)jobs.j[has1 ? j1 : j0].W;
#pragma unroll
        for (int i = 0; i < 4; ++i) {
            int id = i * 256 + tid;
            int k = id >> 4, n = (id & 15) * 4;
            float4 v = Wa[id];
            float* p0 = Wt + (n + 0) * WT_STRIDE + k;
            p0[0 * WT_STRIDE] = v.x; p0[1 * WT_STRIDE] = v.y;
            p0[2 * WT_STRIDE] = v.z; p0[3 * WT_STRIDE] = v.w;
            float4 u = Wb[id];
            float* p1 = Wt + 64 * WT_STRIDE + (n + 0) * WT_STRIDE + k;
            p1[0 * WT_STRIDE] = u.x; p1[1 * WT_STRIDE] = u.y;
            p1[2 * WT_STRIDE] = u.z; p1[3 * WT_STRIDE] = u.w;
        }
    }
    __syncthreads();

    const int warp = tid >> 5, lane = tid & 31;
    const int mat = warp & 1;
    const int rg = warp >> 1;                 // 0..3 -> rows rg*32 .. +31
    const int lr = lane >> 2;                 // 0..7
    const int lc = lane & 3;                  // 0..3
    const float* Xw = Xs + rg * 32 * XS_STRIDE;
    const float* Wm = Wt + mat * 64 * WT_STRIDE;

    float acc[2][8][4];
#pragma unroll
    for (int a = 0; a < 2; ++a)
#pragma unroll
        for (int b = 0; b < 8; ++b)
#pragma unroll
            for (int c = 0; c < 4; ++c) acc[a][b][c] = 0.f;

#pragma unroll
    for (int ks = 0; ks < 8; ++ks) {
        const int k0 = ks * 8;
        unsigned ah[2][4], al[2][4];
#pragma unroll
        for (int mt = 0; mt < 2; ++mt) {
            const float* Xm = Xw + mt * 16 * XS_STRIDE;
            float x0 = Xm[(lr + 0) * XS_STRIDE + k0 + lc];
            float x1 = Xm[(lr + 8) * XS_STRIDE + k0 + lc];
            float x2 = Xm[(lr + 0) * XS_STRIDE + k0 + lc + 4];
            float x3 = Xm[(lr + 8) * XS_STRIDE + k0 + lc + 4];
            split_tf32(x0, ah[mt][0], al[mt][0]);
            split_tf32(x1, ah[mt][1], al[mt][1]);
            split_tf32(x2, ah[mt][2], al[mt][2]);
            split_tf32(x3, ah[mt][3], al[mt][3]);
        }
#pragma unroll
        for (int nt = 0; nt < 8; ++nt) {
            float b0f = Wm[(nt * 8 + lr) * WT_STRIDE + k0 + lc];
            float b1f = Wm[(nt * 8 + lr) * WT_STRIDE + k0 + lc + 4];
            unsigned bh0, bl0, bh1, bl1;
            split_tf32(b0f, bh0, bl0);
            split_tf32(b1f, bh1, bl1);
#pragma unroll
            for (int mt = 0; mt < 2; ++mt) {
                mma_tf32(acc[mt][nt], ah[mt], bh0, bh1);
                mma_tf32(acc[mt][nt], ah[mt], bl0, bl1);
                mma_tf32(acc[mt][nt], al[mt], bh0, bh1);
            }
        }
    }

    const bool valid = (mat == 0) || has1;
    if (!valid) return;
    const int js = (mat && has1) ? j1 : j0;
    const float* Bp = jobs.j[js].B;
    float* Op = jobs.j[js].O;

#pragma unroll
    for (int nt = 0; nt < 8; ++nt) {
        const int c = nt * 8 + 2 * lc;
        float2 bias = *(const float2*)(Bp + c);
#pragma unroll
        for (int mt = 0; mt < 2; ++mt) {
            int r0 = row0 + rg * 32 + mt * 16 + lr;
            if (r0 < N) {
                float2 o = make_float2(acc[mt][nt][0] + bias.x, acc[mt][nt][1] + bias.y);
                *(float2*)(Op + (size_t)r0 * 64 + c) = o;
            }
            int r1 = r0 + 8;
            if (r1 < N) {
                float2 o = make_float2(acc[mt][nt][2] + bias.x, acc[mt][nt][3] + bias.y);
                *(float2*)(Op + (size_t)r1 * 64 + c) = o;
            }
        }
    }
}

// ---------------- sum skip weights over edge types sharing a dest ----------------
__global__ void sumskip(const float* __restrict__ Wl, const float* __restrict__ bl,
                        int t0, int t1, int t2, int t3, int cnt,
                        float* __restrict__ Wsum, float* __restrict__ bsum)
{
    int i = blockIdx.x * blockDim.x + threadIdx.x;
    int ts[4] = {t0, t1, t2, t3};
    if (i < 4096) {
        float s = 0.f;
        for (int j = 0; j < cnt; ++j) s += Wl[ts[j] * 4096 + i];
        Wsum[i] = s;
        if (i < 64) {
            float sb = 0.f;
            for (int j = 0; j < cnt; ++j) sb += bl[ts[j] * 64 + i];
            bsum[i] = sb;
        }
    }
}

// ---------------- CSR build ----------------
__global__ void zero_cnt(int* __restrict__ cnt, int* __restrict__ cursor, int total)
{
    int i = blockIdx.x * blockDim.x + threadIdx.x;
    if (i < total) cnt[i] = 0;
    if (i < 9) cursor[i] = 0;
}

__global__ void count_deg(const int* __restrict__ eidx, int* __restrict__ cnt, int NE)
{
    int t = blockIdx.y;
    int e = blockIdx.x * blockDim.x + threadIdx.x;
    if (e >= NE) return;
    int d = eidx[(size_t)t * 2 * NE + NE + e];
    atomicAdd(&cnt[t * NMAX + d], 1);
}

// warp-aggregated range allocation (replaces serial scan; range order irrelevant)
__global__ void alloc_ranges(const int* __restrict__ cnt, int* __restrict__ cursor,
                             int* __restrict__ rpb, int* __restrict__ cur, int N)
{
    int t = blockIdx.y;
    int i = blockIdx.x * blockDim.x + threadIdx.x;
    int lane = threadIdx.x & 31;
    int deg = (i < N) ? cnt[t * NMAX + i] : 0;
    int v = deg;
#pragma unroll
    for (int off = 1; off < 32; off <<= 1) {
        int u = __shfl_up_sync(0xffffffffu, v, off);
        if (lane >= off) v += u;
    }
    int excl = v - deg;
    int total = __shfl_sync(0xffffffffu, v, 31);
    int base = 0;
    if (lane == 31) base = atomicAdd(&cursor[t], total);
    base = __shfl_sync(0xffffffffu, base, 31);
    if (i < N) {
        rpb[t * NMAX + i] = base + excl;
        cur[t * NMAX + i] = base + excl;
    }
}

__global__ void place_edges(const int* __restrict__ eidx, const float* __restrict__ eattr,
                            int* __restrict__ cur, float4* __restrict__ er, int NE)
{
    int t = blockIdx.y;
    int e = blockIdx.x * blockDim.x + threadIdx.x;
    if (e >= NE) return;
    const int* src = eidx + (size_t)t * 2 * NE;
    const int* dst = src + NE;
    int d = dst[e];
    int s = src[e];
    float2 ea = ((const float2*)(eattr + (size_t)t * NE * 2))[e];
    int pos = atomicAdd(&cur[t * NMAX + d], 1);
    er[(size_t)t * NEMAX + pos] = make_float4(__int_as_float(s), ea.x, ea.y, 0.f);
}

// ---------------- fused edge kernel: warp per destination, online softmax ----------------
__global__ void __launch_bounds__(256) edge_fused(
    const float* __restrict__ P, const int* __restrict__ rpb, const int* __restrict__ cnt,
    const float4* __restrict__ er, const float* __restrict__ WeL,
    float* __restrict__ o1, float* __restrict__ o2, float* __restrict__ o3,
    int N)
{
    const int t = blockIdx.y;
    const float2* Q2 = (const float2*)(P + (size_t)(t * 3 + 0) * PSTRIDE);
    const float2* K2 = (const float2*)(P + (size_t)(t * 3 + 1) * PSTRIDE);
    const float2* V2 = (const float2*)(P + (size_t)(t * 3 + 2) * PSTRIDE);
    const float4* erp = er + (size_t)t * NEMAX;
    const int di = c_dT[t] - 1;
    float* Out = (di == 0) ? o1 : (di == 1) ? o2 : o3;

    const int warp = threadIdx.x >> 5;
    const int lane = threadIdx.x & 31;
    const int d = blockIdx.x * 8 + warp;
    if (d >= N) return;

    const int beg = rpb[t * NMAX + d];
    const int deg = cnt[t * NMAX + d];
    if (deg == 0) return;
    const int end = beg + deg;

    const float2 w0 = ((const float2*)(WeL + t * 128))[lane];
    const float2 w1 = ((const float2*)(WeL + t * 128 + 64))[lane];
    const float2 q = Q2[(size_t)d * 32 + lane];

    // per-dest scalars: qw0 = q . We_row0, qw1 = q . We_row1
    float qw0 = q.x * w0.x + q.y * w0.y;
    float qw1 = q.x * w1.x + q.y * w1.y;
#pragma unroll
    for (int off = 16; off >= 1; off >>= 1) {
        qw0 += __shfl_xor_sync(0xffffffffu, qw0, off);
        qw1 += __shfl_xor_sync(0xffffffffu, qw1, off);
    }

    float m = -3.4e38f, den = 0.f, accx = 0.f, accy = 0.f, sx = 0.f, sy = 0.f;

    int j = beg;
    float4 rec = erp[j];
    int s = __float_as_int(rec.x);
    float2 k2 = K2[(size_t)s * 32 + lane];
    float2 v2 = V2[(size_t)s * 32 + lane];

    while (j < end) {
        float part = q.x * k2.x + q.y * k2.y;
        float vx = v2.x, vy = v2.y;
        float eax = rec.y, eay = rec.z;

        // prefetch next edge while reducing
        int jn = j + 1;
        float4 recn; int sn = 0; float2 k2n, v2n;
        if (jn < end) {
            recn = erp[jn];
            sn = __float_as_int(recn.x);
            k2n = K2[(size_t)sn * 32 + lane];
            v2n = V2[(size_t)sn * 32 + lane];
        }

#pragma unroll
        for (int off = 16; off >= 1; off >>= 1)
            part += __shfl_xor_sync(0xffffffffu, part, off);
        float a = (part + eax * qw0 + eay * qw1) * 0.125f;

        if (a > m) {
            float f = __expf(m - a);
            den *= f; accx *= f; accy *= f; sx *= f; sy *= f;
            m = a;
        }
        float w = __expf(a - m);
        den += w;
        accx += w * vx; accy += w * vy;
        sx += w * eax;  sy += w * eay;

        j = jn; rec = recn; k2 = k2n; v2 = v2n;
    }

    float inv = 1.f / (den + 1e-16f);
    float rx = (accx + sx * w0.x + sy * w1.x) * inv;
    float ry = (accy + sx * w0.y + sy * w1.y) * inv;
    float* p = Out + (size_t)d * 64 + lane * 2;
    asm volatile("red.global.add.v2.f32 [%0], {%1,%2};"
                 :: "l"(p), "f"(rx), "f"(ry) : "memory");
}

// ---------------- final linear (with fused relu on input) ----------------
__global__ void final_lin(const float* __restrict__ X, const float* __restrict__ W,
                          const float* __restrict__ b, float* __restrict__ out, int N)
{
    __shared__ float sW[256];
    int tid = threadIdx.x;
    if (tid < 256) sW[tid] = W[tid];
    __syncthreads();
    int warp = tid >> 5, lane = tid & 31;
    int row = blockIdx.x * 8 + warp;
    if (row >= N) return;
    float2 x2 = ((const float2*)(X + (size_t)row * 64))[lane];
    x2.x = fmaxf(x2.x, 0.f); x2.y = fmaxf(x2.y, 0.f);
    float a0 = x2.x * sW[(2 * lane) * 4 + 0] + x2.y * sW[(2 * lane + 1) * 4 + 0];
    float a1 = x2.x * sW[(2 * lane) * 4 + 1] + x2.y * sW[(2 * lane + 1) * 4 + 1];
    float a2 = x2.x * sW[(2 * lane) * 4 + 2] + x2.y * sW[(2 * lane + 1) * 4 + 2];
    float a3 = x2.x * sW[(2 * lane) * 4 + 3] + x2.y * sW[(2 * lane + 1) * 4 + 3];
#pragma unroll
    for (int off = 16; off >= 1; off >>= 1) {
        a0 += __shfl_down_sync(0xffffffffu, a0, off);
        a1 += __shfl_down_sync(0xffffffffu, a1, off);
        a2 += __shfl_down_sync(0xffffffffu, a2, off);
        a3 += __shfl_down_sync(0xffffffffu, a3, off);
    }
    if (lane == 0) {
        float4 o = make_float4(a0 + b[0], a1 + b[1], a2 + b[2], a3 + b[3]);
        ((float4*)out)[row] = o;
    }
}

// ---------------- host driver ----------------
extern "C" void kernel_launch(void* const* d_in, const int* in_sizes, int n_in,
                              void* d_out, int out_size)
{
    const float* xin[4] = {(const float*)d_in[0], (const float*)d_in[1],
                           (const float*)d_in[2], (const float*)d_in[3]};
    const int*   eidx  = (const int*)d_in[4];
    const float* eattr = (const float*)d_in[5];
    const float* Wq = (const float*)d_in[6];  const float* bq = (const float*)d_in[7];
    const float* Wk = (const float*)d_in[8];  const float* bk = (const float*)d_in[9];
    const float* Wv = (const float*)d_in[10]; const float* bv = (const float*)d_in[11];
    const float* We = (const float*)d_in[12];
    const float* Wsk = (const float*)d_in[13]; const float* bsk = (const float*)d_in[14];
    const float* linW = (const float*)d_in[15]; const float* linb = (const float*)d_in[16];

    const int N  = in_sizes[0] / HH;
    const int NE = in_sizes[5] / (TT * 2);

    float *pP, *pWs, *pBs;
    float *pOa[3], *pOb[3];
    int *pCnt, *pCur, *pRpb, *pCursor;
    float4* pEr;
    cudaGetSymbolAddress((void**)&pP, g_P);
    cudaGetSymbolAddress((void**)&pOa[0], g_outA); pOa[1] = pOa[0] + NMAX * HH; pOa[2] = pOa[1] + NMAX * HH;
    cudaGetSymbolAddress((void**)&pOb[0], g_outB); pOb[1] = pOb[0] + NMAX * HH; pOb[2] = pOb[1] + NMAX * HH;
    cudaGetSymbolAddress((void**)&pCnt, g_cnt);
    cudaGetSymbolAddress((void**)&pCur, g_cur);
    cudaGetSymbolAddress((void**)&pRpb, g_rpb);
    cudaGetSymbolAddress((void**)&pCursor, g_cursor);
    cudaGetSymbolAddress((void**)&pEr, g_er);
    cudaGetSymbolAddress((void**)&pWs, g_Wsum);
    cudaGetSymbolAddress((void**)&pBs, g_bsum);

    cudaFuncSetAttribute(gemm_mma, cudaFuncAttributeMaxDynamicSharedMemorySize, GM_SMEM);

    const int rowTiles = (N + 127) / 128;

    // ---- CSR build (graph static for the whole call) ----
    zero_cnt<<<(9 * NMAX + 255) / 256, 256>>>(pCnt, pCursor, 9 * NMAX);
    count_deg<<<dim3((NE + 255) / 256, 9), 256>>>(eidx, pCnt, NE);
    alloc_ranges<<<dim3((N + 255) / 256, 9), 256>>>(pCnt, pCursor, pRpb, pCur, N);
    place_edges<<<dim3((NE + 255) / 256, 9), 256>>>(eidx, eattr, pCur, pEr, NE);

    for (int l = 0; l < 2; ++l) {
        const float* xc[4];
        float** pO;
        int dorelu;
        if (l == 0) { xc[0] = xin[0]; xc[1] = xin[1]; xc[2] = xin[2]; xc[3] = xin[3]; pO = pOa; dorelu = 0; }
        else        { xc[0] = xin[0]; xc[1] = pOa[0]; xc[2] = pOa[1]; xc[3] = pOa[2]; pO = pOb; dorelu = 1; }

        const int wb = l * TT;
        const float* Wsl = Wsk + (size_t)wb * 4096;
        const float* bsl = bsk + (size_t)wb * 64;

        sumskip<<<16, 256>>>(Wsl, bsl, 0, 5, 0, 0, 2, pWs + 0 * 4096, pBs + 0 * 64);
        sumskip<<<16, 256>>>(Wsl, bsl, 1, 3, 7, 0, 3, pWs + 1 * 4096, pBs + 1 * 64);
        sumskip<<<16, 256>>>(Wsl, bsl, 2, 4, 6, 8, 4, pWs + 2 * 4096, pBs + 2 * 64);

        auto WQ = [&](int t){ return Wq + (size_t)(wb + t) * 4096; };
        auto BQ = [&](int t){ return bq + (size_t)(wb + t) * 64; };
        auto WK = [&](int t){ return Wk + (size_t)(wb + t) * 4096; };
        auto BK = [&](int t){ return bk + (size_t)(wb + t) * 64; };
        auto WV = [&](int t){ return Wv + (size_t)(wb + t) * 4096; };
        auto BV = [&](int t){ return bv + (size_t)(wb + t) * 64; };
        auto PP = [&](int t, int role){ return pP + (size_t)(t * 3 + role) * PSTRIDE; };

        // x0 (SB): K/V for t=0,1,2  (xs[0] is never updated/relu'd)
        {
            Jobs J{}; int n = 0;
            for (int t = 0; t <= 2; ++t) {
                J.j[n++] = {WK(t), BK(t), PP(t, 1)};
                J.j[n++] = {WV(t), BV(t), PP(t, 2)};
            }
            gemm_mma<<<dim3(rowTiles, (n + 1) / 2), 256, GM_SMEM>>>(xc[0], J, n, N, 0);
        }
        // x1 (PV): K/V t=3,4,5; Q t=0,5; skip d1
        {
            Jobs J{}; int n = 0;
            for (int t = 3; t <= 5; ++t) {
                J.j[n++] = {WK(t), BK(t), PP(t, 1)};
                J.j[n++] = {WV(t), BV(t), PP(t, 2)};
            }
            J.j[n++] = {WQ(0), BQ(0), PP(0, 0)};
            J.j[n++] = {WQ(5), BQ(5), PP(5, 0)};
            J.j[n++] = {pWs + 0 * 4096, pBs + 0 * 64, pO[0]};
            gemm_mma<<<dim3(rowTiles, (n + 1) / 2), 256, GM_SMEM>>>(xc[1], J, n, N, dorelu);
        }
        // x2 (PQ): K/V t=6,7; Q t=1,3,7; skip d2
        {
            Jobs J{}; int n = 0;
            for (int t = 6; t <= 7; ++t) {
                J.j[n++] = {WK(t), BK(t), PP(t, 1)};
                J.j[n++] = {WV(t), BV(t), PP(t, 2)};
            }
            J.j[n++] = {WQ(1), BQ(1), PP(1, 0)};
            J.j[n++] = {WQ(3), BQ(3), PP(3, 0)};
            J.j[n++] = {WQ(7), BQ(7), PP(7, 0)};
            J.j[n++] = {pWs + 1 * 4096, pBs + 1 * 64, pO[1]};
            gemm_mma<<<dim3(rowTiles, (n + 1) / 2), 256, GM_SMEM>>>(xc[2], J, n, N, dorelu);
        }
        // x3 (NB): K/V t=8; Q t=2,4,6,8; skip d3
        {
            Jobs J{}; int n = 0;
            J.j[n++] = {WK(8), BK(8), PP(8, 1)};
            J.j[n++] = {WV(8), BV(8), PP(8, 2)};
            J.j[n++] = {WQ(2), BQ(2), PP(2, 0)};
            J.j[n++] = {WQ(4), BQ(4), PP(4, 0)};
            J.j[n++] = {WQ(6), BQ(6), PP(6, 0)};
            J.j[n++] = {WQ(8), BQ(8), PP(8, 0)};
            J.j[n++] = {pWs + 2 * 4096, pBs + 2 * 64, pO[2]};
            gemm_mma<<<dim3(rowTiles, (n + 1) / 2), 256, GM_SMEM>>>(xc[3], J, n, N, dorelu);
        }

        // fused edge aggregation, all 9 types
        const float* WeL = We + (size_t)wb * 128;
        edge_fused<<<dim3((N + 7) / 8, 9), 256>>>(pP, pRpb, pCnt, pEr, WeL,
                                                  pO[0], pO[1], pO[2], N);
    }

    // final linear on relu(PQ) (dest index 2 -> pOb[1])
    final_lin<<<(N + 7) / 8, 256>>>(pOb[1], linW, linb, (float*)d_out, N);
}